// round 8
// baseline (speedup 1.0000x reference)
#include <cuda_runtime.h>
#include <cuda_fp16.h>
#include <cuda_bf16.h>
#include <math.h>
#include <stdint.h>

#define SEQ    2048
#define DM     768
#define DI     1536
#define DS     16
#define DTR    48
#define NLAYER 4
#define NVOCAB 50264

// ---------------- fp32 scratch ----------------
__device__ float g_x   [SEQ * DM];
__device__ float g_xz  [SEQ * 2 * DI];
__device__ float g_xi  [SEQ * DI];
__device__ float g_xdbl[SEQ * 80];
__device__ float g_delta[SEQ * DI];

// ---------------- fp16 scratch ----------------
__device__ __half g_emb16 [NVOCAB * DM];
__device__ __half g_inw16 [NLAYER * 2 * DI * DM];
__device__ __half g_xpw16 [NLAYER * 80 * DI];
__device__ __half g_outw16[NLAYER * DM * DI];
__device__ __half g_acth  [SEQ * DI];
__device__ __half g_actl  [SEQ * DI];

__device__ __forceinline__ void split1h(float v, __half& h, __half& l) {
    h = __float2half_rn(v);
    l = __float2half_rn(v - __half2float(h));
}
__device__ __forceinline__ uint32_t smem_u32(const void* p) {
    uint32_t a;
    asm("{ .reg .u64 t; cvta.to.shared.u64 t, %1; cvt.u32.u64 %0, t; }"
        : "=r"(a) : "l"(p));
    return a;
}

// ---------------- weight fp32 -> fp16 round ----------------
__global__ void round_kernel(const float* __restrict__ x,
                             __half* __restrict__ o, int n4) {
    int i = blockIdx.x * blockDim.x + threadIdx.x;
    if (i >= n4) return;
    float4 v = ((const float4*)x)[i];
    __half2 h01 = __floats2half2_rn(v.x, v.y);
    __half2 h23 = __floats2half2_rn(v.z, v.w);
    ((uint2*)o)[i] = make_uint2(*(uint32_t*)&h01, *(uint32_t*)&h23);
}

// ---------------- embedding gather ----------------
__global__ void embed_kernel(const int* __restrict__ ids,
                             const float* __restrict__ emb,
                             float* __restrict__ x) {
    int t = blockIdx.x;
    int id = ids[t];
    const float* src = emb + (size_t)id * DM;
    float* dst = x + (size_t)t * DM;
    for (int c = threadIdx.x; c < DM; c += 256) dst[c] = src[c];
}

// ---------------- rmsnorm with fp16 split output ----------------
__global__ void rmsnorm_split_kernel(const float* __restrict__ x,
                                     const float* __restrict__ w,
                                     __half* __restrict__ ohi,
                                     __half* __restrict__ olo) {
    int row = blockIdx.x;
    const float* xr = x + (size_t)row * DM;
    float ss = 0.f;
    for (int c = threadIdx.x; c < DM; c += 256) { float v = xr[c]; ss += v * v; }
    #pragma unroll
    for (int o = 16; o; o >>= 1) ss += __shfl_xor_sync(0xffffffffu, ss, o);
    __shared__ float sred[8];
    if ((threadIdx.x & 31) == 0) sred[threadIdx.x >> 5] = ss;
    __syncthreads();
    if (threadIdx.x < 8) {
        float v = sred[threadIdx.x];
        #pragma unroll
        for (int o = 4; o; o >>= 1) v += __shfl_xor_sync(0xffu, v, o);
        if (threadIdx.x == 0) sred[0] = v;
    }
    __syncthreads();
    float scale = rsqrtf(sred[0] / (float)DM + 1e-5f);
    for (int c = threadIdx.x; c < DM; c += 256) {
        float v = xr[c] * scale * w[c];
        __half h, l;
        split1h(v, h, l);
        ohi[(size_t)row * DM + c] = h;
        olo[(size_t)row * DM + c] = l;
    }
}

// ---------------- conv + silu, fp32 + fp16 split outputs ----------------
__global__ void conv_silu_kernel(const float* __restrict__ xz,
                                 const float* __restrict__ cw,
                                 const float* __restrict__ cb,
                                 float* __restrict__ xi,
                                 __half* __restrict__ ohi,
                                 __half* __restrict__ olo) {
    int idx = blockIdx.x * blockDim.x + threadIdx.x;
    if (idx >= SEQ * DI) return;
    int t = idx / DI;
    int d = idx - t * DI;
    float acc = cb[d];
    #pragma unroll
    for (int k = 0; k < 4; k++) {
        int tt = t - 3 + k;
        if (tt >= 0) acc = fmaf(xz[(size_t)tt * (2 * DI) + d], cw[d * 4 + k], acc);
    }
    float v = acc / (1.f + __expf(-acc));
    xi[idx] = v;
    __half h, l;
    split1h(v, h, l);
    ohi[idx] = h;
    olo[idx] = l;
}

// ---------------- dt_proj (K=48) + softplus ----------------
__global__ void __launch_bounds__(128)
dtproj_kernel(const float* __restrict__ xdbl, const float* __restrict__ W,
              const float* __restrict__ b, float* __restrict__ delta) {
    int d = blockIdx.x * 128 + threadIdx.x;
    int t0 = blockIdx.y * 16;
    __shared__ float sx[16][DTR];
    for (int i = threadIdx.x; i < 16 * DTR; i += 128) {
        int tt = i / DTR, r = i - tt * DTR;
        sx[tt][r] = xdbl[(size_t)(t0 + tt) * 80 + r];
    }
    float w[DTR];
    #pragma unroll
    for (int r = 0; r < DTR; r++) w[r] = W[(size_t)d * DTR + r];
    float bias = b[d];
    __syncthreads();
    for (int tt = 0; tt < 16; tt++) {
        float acc = bias;
        #pragma unroll
        for (int r = 0; r < DTR; r++) acc = fmaf(sx[tt][r], w[r], acc);
        float sp = fmaxf(acc, 0.f) + log1pf(__expf(-fabsf(acc)));
        delta[(size_t)(t0 + tt) * DI + d] = sp;
    }
}

// ---------------- selective scan + gating, fp16 split output ----------------
#define SCAN_T 64
__global__ void __launch_bounds__(128)
scan_kernel(const float* __restrict__ xdbl, const float* __restrict__ delta,
            const float* __restrict__ xi, const float* __restrict__ xz,
            const float* __restrict__ A_log, const float* __restrict__ Dp,
            __half* __restrict__ yhi, __half* __restrict__ ylo) {
    __shared__ float sB[SCAN_T][16];
    __shared__ float sC[SCAN_T][16];
    __shared__ float sDt[SCAN_T][8];
    __shared__ float sU[SCAN_T][8];
    __shared__ float sRes[SCAN_T][8];
    __shared__ float sY[SCAN_T][8];

    int tid = threadIdx.x;
    int lane = tid & 31;
    int warp = tid >> 5;
    int ch = (warp << 1) | (lane >> 4);
    int n = lane & 15;
    int d0 = blockIdx.x * 8;
    int d = d0 + ch;

    float a = -__expf(A_log[(size_t)d * DS + n]);
    float Dv = Dp[d];
    float h = 0.f;

    for (int t0 = 0; t0 < SEQ; t0 += SCAN_T) {
        for (int i = tid; i < SCAN_T * 16; i += 128) {
            int tt = i >> 4, j = i & 15;
            size_t base = (size_t)(t0 + tt) * 80;
            sB[tt][j] = xdbl[base + DTR + j];
            sC[tt][j] = xdbl[base + DTR + DS + j];
        }
        for (int i = tid; i < SCAN_T * 8; i += 128) {
            int tt = i >> 3, j = i & 7;
            sDt[tt][j]  = delta[(size_t)(t0 + tt) * DI + d0 + j];
            sU[tt][j]   = xi[(size_t)(t0 + tt) * DI + d0 + j];
            sRes[tt][j] = xz[(size_t)(t0 + tt) * (2 * DI) + DI + d0 + j];
        }
        __syncthreads();
        #pragma unroll 4
        for (int tt = 0; tt < SCAN_T; tt++) {
            float dt = sDt[tt][ch];
            float u  = sU[tt][ch];
            float Bt = sB[tt][n];
            float Ct = sC[tt][n];
            float dA = __expf(dt * a);
            h = fmaf(dA, h, dt * Bt * u);
            float p = h * Ct;
            p += __shfl_xor_sync(0xffffffffu, p, 1);
            p += __shfl_xor_sync(0xffffffffu, p, 2);
            p += __shfl_xor_sync(0xffffffffu, p, 4);
            p += __shfl_xor_sync(0xffffffffu, p, 8);
            if (n == 0) {
                float res = sRes[tt][ch];
                float g = res / (1.f + __expf(-res));
                sY[tt][ch] = (p + u * Dv) * g;
            }
        }
        __syncthreads();
        for (int i = tid; i < SCAN_T * 8; i += 128) {
            int tt = i >> 3, j = i & 7;
            float v = sY[tt][j];
            __half hh, ll;
            split1h(v, hh, ll);
            size_t o = (size_t)(t0 + tt) * DI + d0 + j;
            yhi[o] = hh;
            ylo[o] = ll;
        }
        __syncthreads();
    }
}

// ================= HMMA fp16 2-term GEMM, BK=64 ============================
// C[M,N] = (Ahi+Alo)[M,K] @ Bh[N,K]^T (+R).
// BM=BN=128, BK=64, 256 thr, 8 warps (2x4), warp tile 64x32.
// 3-stage cp.async pipeline + intra-chunk ldmatrix double buffering.
#define SPADB  144                  // 128 data bytes + 16 pad
#define STG_M  (128 * SPADB)        // 18432 B per matrix
#define STG_BYTES (3 * STG_M)       // Ahi, Alo, Bh = 55296
#define NSTAGE 3
#define GSMEM  (NSTAGE * STG_BYTES) // 165888

#define LDSM4(r0, r1, r2, r3, addr) \
    asm volatile("ldmatrix.sync.aligned.m8n8.x4.shared.b16 {%0,%1,%2,%3}, [%4];" \
        : "=r"(r0), "=r"(r1), "=r"(r2), "=r"(r3) : "r"(addr))

#define MMA16816(c, a, b) \
    asm volatile("mma.sync.aligned.m16n8k16.row.col.f32.f16.f16.f32 " \
        "{%0,%1,%2,%3},{%4,%5,%6,%7},{%8,%9},{%0,%1,%2,%3};" \
        : "+f"((c)[0]), "+f"((c)[1]), "+f"((c)[2]), "+f"((c)[3]) \
        : "r"((a)[0]), "r"((a)[1]), "r"((a)[2]), "r"((a)[3]), \
          "r"((b)[0]), "r"((b)[1]))

__device__ __forceinline__ void cpa16(uint32_t dst, const void* src, int sz) {
    asm volatile("cp.async.ca.shared.global [%0], [%1], 16, %2;"
                 :: "r"(dst), "l"(src), "r"(sz) : "memory");
}

__global__ void __launch_bounds__(256)
mma_gemm(const __half* __restrict__ Ahi, const __half* __restrict__ Alo,
         const __half* __restrict__ Bh,
         float* __restrict__ C, const float* __restrict__ R, int N, int K) {
    extern __shared__ char dsm[];
    const int tid  = threadIdx.x;
    const int lane = tid & 31;
    const int wid  = tid >> 5;
    const int wm   = wid >> 2;
    const int wn   = wid & 3;
    const int m0 = blockIdx.x * 128;
    const int n0 = blockIdx.y * 128;
    const uint32_t sb = smem_u32(dsm);

    // cp.async mapping: row = tid>>1, 64B half = (tid&1)
    const int crow  = tid >> 1;
    const int chalf = tid & 1;

    const int rowA = wm * 64 + (lane & 15);
    const int offA = rowA * SPADB + (lane >> 4) * 16;
    const int rowB = wn * 32 + (lane & 7) + ((lane & 16) >> 1);
    const int offB = rowB * SPADB + (lane & 8) * 2;

    float acc[4][4][4];
    #pragma unroll
    for (int i = 0; i < 4; i++)
        #pragma unroll
        for (int j = 0; j < 4; j++)
            #pragma unroll
            for (int q = 0; q < 4; q++) acc[i][j][q] = 0.f;

    const int NCH = K >> 6;   // BK = 64

    auto issue = [&](int c) {
        int k0 = c * 64;
        uint32_t st = sb + (c % NSTAGE) * STG_BYTES;
        uint32_t so = (uint32_t)(crow * SPADB + chalf * 64);
        size_t gkA = (size_t)(m0 + crow) * K + k0 + chalf * 32;
        #pragma unroll
        for (int s = 0; s < 4; s++)
            cpa16(st + so + s * 16, Ahi + gkA + s * 8, 16);
        #pragma unroll
        for (int s = 0; s < 4; s++)
            cpa16(st + STG_M + so + s * 16, Alo + gkA + s * 8, 16);
        int nb = n0 + crow;
        int sz = (nb < N) ? 16 : 0;
        size_t gkB = (size_t)((nb < N) ? nb : (N - 1)) * K + k0 + chalf * 32;
        #pragma unroll
        for (int s = 0; s < 4; s++)
            cpa16(st + 2 * STG_M + so + s * 16, Bh + gkB + s * 8, sz);
    };

    issue(0);
    asm volatile("cp.async.commit_group;" ::: "memory");
    issue(1);
    asm volatile("cp.async.commit_group;" ::: "memory");

    uint32_t ah[2][4][4], al[2][4][4], bh[2][4][2];

    auto ldfrag = [&](uint32_t st, int ks, int buf) {
        #pragma unroll
        for (int mt = 0; mt < 4; mt++) {
            uint32_t o = st + offA + mt * 16 * SPADB + ks * 32;
            LDSM4(ah[buf][mt][0], ah[buf][mt][1], ah[buf][mt][2], ah[buf][mt][3], o);
            LDSM4(al[buf][mt][0], al[buf][mt][1], al[buf][mt][2], al[buf][mt][3], o + STG_M);
        }
        #pragma unroll
        for (int np = 0; np < 2; np++) {
            uint32_t o = st + 2 * STG_M + offB + np * 16 * SPADB + ks * 32;
            uint32_t r0, r1, r2, r3;
            LDSM4(r0, r1, r2, r3, o);
            bh[buf][np * 2][0] = r0; bh[buf][np * 2][1] = r1;
            bh[buf][np * 2 + 1][0] = r2; bh[buf][np * 2 + 1][1] = r3;
        }
    };

    for (int c = 0; c < NCH; c++) {
        asm volatile("cp.async.wait_group 1;" ::: "memory");
        __syncthreads();
        if (c + 2 < NCH) issue(c + 2);
        asm volatile("cp.async.commit_group;" ::: "memory");

        uint32_t st = sb + (c % NSTAGE) * STG_BYTES;
        ldfrag(st, 0, 0);
        #pragma unroll
        for (int ks = 0; ks < 4; ks++) {
            int cur = ks & 1;
            if (ks < 3) ldfrag(st, ks + 1, cur ^ 1);
            #pragma unroll
            for (int mt = 0; mt < 4; mt++)
                #pragma unroll
                for (int nt = 0; nt < 4; nt++) {
                    MMA16816(acc[mt][nt], ah[cur][mt], bh[cur][nt]);
                    MMA16816(acc[mt][nt], al[cur][mt], bh[cur][nt]);
                }
        }
    }

    // epilogue
    #pragma unroll
    for (int mt = 0; mt < 4; mt++) {
        int row = m0 + wm * 64 + mt * 16 + (lane >> 2);
        #pragma unroll
        for (int nt = 0; nt < 4; nt++) {
            int col = n0 + wn * 32 + nt * 8 + (lane & 3) * 2;
            if (col < N) {
                size_t o0 = (size_t)row * N + col;
                size_t o1 = (size_t)(row + 8) * N + col;
                float2 v0 = make_float2(acc[mt][nt][0], acc[mt][nt][1]);
                float2 v1 = make_float2(acc[mt][nt][2], acc[mt][nt][3]);
                if (R) {
                    float2 r0 = *(const float2*)(R + o0);
                    float2 r1 = *(const float2*)(R + o1);
                    v0.x += r0.x; v0.y += r0.y;
                    v1.x += r1.x; v1.y += r1.y;
                }
                *(float2*)(C + o0) = v0;
                *(float2*)(C + o1) = v1;
            }
        }
    }
}

// ================= host orchestration ======================================
extern "C" void kernel_launch(void* const* d_in, const int* in_sizes, int n_in,
                              void* d_out, int out_size) {
    (void)in_sizes; (void)n_in; (void)out_size;
    const int*   input_ids = (const int*)  d_in[0];
    const float* emb       = (const float*)d_in[1];
    const float* in_proj_w = (const float*)d_in[2];
    const float* conv_w    = (const float*)d_in[3];
    const float* conv_b    = (const float*)d_in[4];
    const float* x_proj_w  = (const float*)d_in[5];
    const float* dt_proj_w = (const float*)d_in[6];
    const float* dt_proj_b = (const float*)d_in[7];
    const float* A_log     = (const float*)d_in[8];
    const float* D_param   = (const float*)d_in[9];
    const float* out_proj_w= (const float*)d_in[10];
    const float* norm_w    = (const float*)d_in[11];
    const float* norm_f_w  = (const float*)d_in[12];
    float* logits = (float*)d_out;

    float *px, *pxz, *pxi, *pxdbl, *pdelta;
    __half *pemb16, *pinw16, *pxpw16, *poutw16, *pacth, *pactl;
    cudaGetSymbolAddress((void**)&px,      g_x);
    cudaGetSymbolAddress((void**)&pxz,     g_xz);
    cudaGetSymbolAddress((void**)&pxi,     g_xi);
    cudaGetSymbolAddress((void**)&pxdbl,   g_xdbl);
    cudaGetSymbolAddress((void**)&pdelta,  g_delta);
    cudaGetSymbolAddress((void**)&pemb16,  g_emb16);
    cudaGetSymbolAddress((void**)&pinw16,  g_inw16);
    cudaGetSymbolAddress((void**)&pxpw16,  g_xpw16);
    cudaGetSymbolAddress((void**)&poutw16, g_outw16);
    cudaGetSymbolAddress((void**)&pacth,   g_acth);
    cudaGetSymbolAddress((void**)&pactl,   g_actl);

    cudaFuncSetAttribute(mma_gemm, cudaFuncAttributeMaxDynamicSharedMemorySize, GSMEM);

    // weight fp16 rounding (once per launch)
    {
        int n4 = NVOCAB * DM / 4;
        round_kernel<<<(n4 + 255) / 256, 256>>>(emb, pemb16, n4);
        n4 = NLAYER * 2 * DI * DM / 4;
        round_kernel<<<(n4 + 255) / 256, 256>>>(in_proj_w, pinw16, n4);
        n4 = NLAYER * 80 * DI / 4;
        round_kernel<<<(n4 + 255) / 256, 256>>>(x_proj_w, pxpw16, n4);
        n4 = NLAYER * DM * DI / 4;
        round_kernel<<<(n4 + 255) / 256, 256>>>(out_proj_w, poutw16, n4);
    }

    embed_kernel<<<SEQ, 256>>>(input_ids, emb, px);

    for (int i = 0; i < NLAYER; i++) {
        rmsnorm_split_kernel<<<SEQ, 256>>>(px, norm_w + (size_t)i * DM, pacth, pactl);
        // in_proj: (2048,768) x (3072,768)^T
        mma_gemm<<<dim3(SEQ / 128, 2 * DI / 128), 256, GSMEM>>>(
            pacth, pactl, pinw16 + (size_t)i * 2 * DI * DM,
            pxz, nullptr, 2 * DI, DM);
        conv_silu_kernel<<<(SEQ * DI + 255) / 256, 256>>>(
            pxz, conv_w + (size_t)i * DI * 4, conv_b + (size_t)i * DI,
            pxi, pacth, pactl);
        // x_proj: (2048,1536) x (80,1536)^T
        mma_gemm<<<dim3(SEQ / 128, 1), 256, GSMEM>>>(
            pacth, pactl, pxpw16 + (size_t)i * 80 * DI,
            pxdbl, nullptr, 80, DI);
        dtproj_kernel<<<dim3(DI / 128, SEQ / 16), 128>>>(
            pxdbl, dt_proj_w + (size_t)i * DI * DTR, dt_proj_b + (size_t)i * DI, pdelta);
        scan_kernel<<<DI / 8, 128>>>(
            pxdbl, pdelta, pxi, pxz,
            A_log + (size_t)i * DI * DS, D_param + (size_t)i * DI, pacth, pactl);
        // out_proj + residual
        mma_gemm<<<dim3(SEQ / 128, DM / 128), 256, GSMEM>>>(
            pacth, pactl, poutw16 + (size_t)i * DM * DI,
            px, px, DM, DI);
    }

    rmsnorm_split_kernel<<<SEQ, 256>>>(px, norm_f_w, pacth, pactl);
    // logits: (2048,768) x (50264,768)^T
    mma_gemm<<<dim3(SEQ / 128, (NVOCAB + 127) / 128), 256, GSMEM>>>(
        pacth, pactl, pemb16, logits, nullptr, NVOCAB, DM);
}

// round 10
// speedup vs baseline: 1.0694x; 1.0694x over previous
#include <cuda_runtime.h>
#include <cuda_fp16.h>
#include <math.h>
#include <stdint.h>

#define SEQ    2048
#define DM     768
#define DI     1536
#define DS     16
#define DTR    48
#define NLAYER 4
#define NVOCAB 50264

// ---------------- fp32 scratch ----------------
__device__ float g_x   [SEQ * DM];
__device__ float g_xz  [SEQ * 2 * DI];
__device__ float g_xi  [SEQ * DI];
__device__ float g_xdbl[SEQ * 80];
__device__ float g_delta[SEQ * DI];

// ---------------- fp16 scratch ----------------
__device__ __half g_emb16 [NVOCAB * DM];
__device__ __half g_inw16 [NLAYER * 2 * DI * DM];
__device__ __half g_xpw16 [NLAYER * 80 * DI];
__device__ __half g_outw16[NLAYER * DM * DI];
__device__ __half g_acth  [SEQ * DI];
__device__ __half g_actl  [SEQ * DI];

__device__ __forceinline__ void split1h(float v, __half& h, __half& l) {
    h = __float2half_rn(v);
    l = __float2half_rn(v - __half2float(h));
}
__device__ __forceinline__ uint32_t smem_u32(const void* p) {
    uint32_t a;
    asm("{ .reg .u64 t; cvta.to.shared.u64 t, %1; cvt.u32.u64 %0, t; }"
        : "=r"(a) : "l"(p));
    return a;
}

// ---------------- weight fp32 -> fp16 round ----------------
__global__ void round_kernel(const float* __restrict__ x,
                             __half* __restrict__ o, int n4) {
    int i = blockIdx.x * blockDim.x + threadIdx.x;
    if (i >= n4) return;
    float4 v = ((const float4*)x)[i];
    __half2 h01 = __floats2half2_rn(v.x, v.y);
    __half2 h23 = __floats2half2_rn(v.z, v.w);
    ((uint2*)o)[i] = make_uint2(*(uint32_t*)&h01, *(uint32_t*)&h23);
}

// ---------------- embedding gather ----------------
__global__ void embed_kernel(const int* __restrict__ ids,
                             const float* __restrict__ emb,
                             float* __restrict__ x) {
    int t = blockIdx.x;
    int id = ids[t];
    const float* src = emb + (size_t)id * DM;
    float* dst = x + (size_t)t * DM;
    for (int c = threadIdx.x; c < DM; c += 256) dst[c] = src[c];
}

// ---------------- rmsnorm with fp16 split output ----------------
__global__ void rmsnorm_split_kernel(const float* __restrict__ x,
                                     const float* __restrict__ w,
                                     __half* __restrict__ ohi,
                                     __half* __restrict__ olo) {
    int row = blockIdx.x;
    const float* xr = x + (size_t)row * DM;
    float ss = 0.f;
    for (int c = threadIdx.x; c < DM; c += 256) { float v = xr[c]; ss += v * v; }
    #pragma unroll
    for (int o = 16; o; o >>= 1) ss += __shfl_xor_sync(0xffffffffu, ss, o);
    __shared__ float sred[8];
    if ((threadIdx.x & 31) == 0) sred[threadIdx.x >> 5] = ss;
    __syncthreads();
    if (threadIdx.x < 8) {
        float v = sred[threadIdx.x];
        #pragma unroll
        for (int o = 4; o; o >>= 1) v += __shfl_xor_sync(0xffu, v, o);
        if (threadIdx.x == 0) sred[0] = v;
    }
    __syncthreads();
    float scale = rsqrtf(sred[0] / (float)DM + 1e-5f);
    for (int c = threadIdx.x; c < DM; c += 256) {
        float v = xr[c] * scale * w[c];
        __half h, l;
        split1h(v, h, l);
        ohi[(size_t)row * DM + c] = h;
        olo[(size_t)row * DM + c] = l;
    }
}

// ---------------- conv + silu, fp32 + fp16 split outputs ----------------
__global__ void conv_silu_kernel(const float* __restrict__ xz,
                                 const float* __restrict__ cw,
                                 const float* __restrict__ cb,
                                 float* __restrict__ xi,
                                 __half* __restrict__ ohi,
                                 __half* __restrict__ olo) {
    int idx = blockIdx.x * blockDim.x + threadIdx.x;
    if (idx >= SEQ * DI) return;
    int t = idx / DI;
    int d = idx - t * DI;
    float acc = cb[d];
    #pragma unroll
    for (int k = 0; k < 4; k++) {
        int tt = t - 3 + k;
        if (tt >= 0) acc = fmaf(xz[(size_t)tt * (2 * DI) + d], cw[d * 4 + k], acc);
    }
    float v = acc / (1.f + __expf(-acc));
    xi[idx] = v;
    __half h, l;
    split1h(v, h, l);
    ohi[idx] = h;
    olo[idx] = l;
}

// ---------------- dt_proj (K=48) + softplus ----------------
__global__ void __launch_bounds__(128)
dtproj_kernel(const float* __restrict__ xdbl, const float* __restrict__ W,
              const float* __restrict__ b, float* __restrict__ delta) {
    int d = blockIdx.x * 128 + threadIdx.x;
    int t0 = blockIdx.y * 16;
    __shared__ float sx[16][DTR];
    for (int i = threadIdx.x; i < 16 * DTR; i += 128) {
        int tt = i / DTR, r = i - tt * DTR;
        sx[tt][r] = xdbl[(size_t)(t0 + tt) * 80 + r];
    }
    float w[DTR];
    #pragma unroll
    for (int r = 0; r < DTR; r++) w[r] = W[(size_t)d * DTR + r];
    float bias = b[d];
    __syncthreads();
    for (int tt = 0; tt < 16; tt++) {
        float acc = bias;
        #pragma unroll
        for (int r = 0; r < DTR; r++) acc = fmaf(sx[tt][r], w[r], acc);
        float sp = fmaxf(acc, 0.f) + log1pf(__expf(-fabsf(acc)));
        delta[(size_t)(t0 + tt) * DI + d] = sp;
    }
}

// ---------------- selective scan + gating, fp16 split output ----------------
#define SCAN_T 64
__global__ void __launch_bounds__(128)
scan_kernel(const float* __restrict__ xdbl, const float* __restrict__ delta,
            const float* __restrict__ xi, const float* __restrict__ xz,
            const float* __restrict__ A_log, const float* __restrict__ Dp,
            __half* __restrict__ yhi, __half* __restrict__ ylo) {
    __shared__ float sB[SCAN_T][16];
    __shared__ float sC[SCAN_T][16];
    __shared__ float sDt[SCAN_T][8];
    __shared__ float sU[SCAN_T][8];
    __shared__ float sRes[SCAN_T][8];
    __shared__ float sY[SCAN_T][8];

    int tid = threadIdx.x;
    int lane = tid & 31;
    int warp = tid >> 5;
    int ch = (warp << 1) | (lane >> 4);
    int n = lane & 15;
    int d0 = blockIdx.x * 8;
    int d = d0 + ch;

    float a = -__expf(A_log[(size_t)d * DS + n]);
    float Dv = Dp[d];
    float h = 0.f;

    for (int t0 = 0; t0 < SEQ; t0 += SCAN_T) {
        for (int i = tid; i < SCAN_T * 16; i += 128) {
            int tt = i >> 4, j = i & 15;
            size_t base = (size_t)(t0 + tt) * 80;
            sB[tt][j] = xdbl[base + DTR + j];
            sC[tt][j] = xdbl[base + DTR + DS + j];
        }
        for (int i = tid; i < SCAN_T * 8; i += 128) {
            int tt = i >> 3, j = i & 7;
            sDt[tt][j]  = delta[(size_t)(t0 + tt) * DI + d0 + j];
            sU[tt][j]   = xi[(size_t)(t0 + tt) * DI + d0 + j];
            sRes[tt][j] = xz[(size_t)(t0 + tt) * (2 * DI) + DI + d0 + j];
        }
        __syncthreads();
        #pragma unroll 4
        for (int tt = 0; tt < SCAN_T; tt++) {
            float dt = sDt[tt][ch];
            float u  = sU[tt][ch];
            float Bt = sB[tt][n];
            float Ct = sC[tt][n];
            float dA = __expf(dt * a);
            h = fmaf(dA, h, dt * Bt * u);
            float p = h * Ct;
            p += __shfl_xor_sync(0xffffffffu, p, 1);
            p += __shfl_xor_sync(0xffffffffu, p, 2);
            p += __shfl_xor_sync(0xffffffffu, p, 4);
            p += __shfl_xor_sync(0xffffffffu, p, 8);
            if (n == 0) {
                float res = sRes[tt][ch];
                float g = res / (1.f + __expf(-res));
                sY[tt][ch] = (p + u * Dv) * g;
            }
        }
        __syncthreads();
        for (int i = tid; i < SCAN_T * 8; i += 128) {
            int tt = i >> 3, j = i & 7;
            float v = sY[tt][j];
            __half hh, ll;
            split1h(v, hh, ll);
            size_t o = (size_t)(t0 + tt) * DI + d0 + j;
            yhi[o] = hh;
            ylo[o] = ll;
        }
        __syncthreads();
    }
}

// ================= HMMA fp16 2-term GEMM ===================================
// C[M,N] = (Ahi+Alo)[M,K] @ Bh[N,K]^T (+R).  Dropped term A*(B-fp16(B)) ~ 2^-12.
// BM=BN=128, BK=32, 256 thr, 8 warps (2x4), warp tile 64x32.
// 3-stage cp.async pipeline; 2 CTAs/SM via launch bounds (4 warps/SMSP).
#define SPADB  80
#define STG_M  (128 * SPADB)        // 10240 B per matrix
#define STG_BYTES (3 * STG_M)       // Ahi, Alo, Bh
#define NSTAGE 3
#define GSMEM  (NSTAGE * STG_BYTES) // 92160; x2 CTAs = 184320 < 227KB

#define LDSM4(r0, r1, r2, r3, addr) \
    asm volatile("ldmatrix.sync.aligned.m8n8.x4.shared.b16 {%0,%1,%2,%3}, [%4];" \
        : "=r"(r0), "=r"(r1), "=r"(r2), "=r"(r3) : "r"(addr))

#define MMA16816(c, a, b) \
    asm volatile("mma.sync.aligned.m16n8k16.row.col.f32.f16.f16.f32 " \
        "{%0,%1,%2,%3},{%4,%5,%6,%7},{%8,%9},{%0,%1,%2,%3};" \
        : "+f"((c)[0]), "+f"((c)[1]), "+f"((c)[2]), "+f"((c)[3]) \
        : "r"((a)[0]), "r"((a)[1]), "r"((a)[2]), "r"((a)[3]), \
          "r"((b)[0]), "r"((b)[1]))

__device__ __forceinline__ void cpa16(uint32_t dst, const void* src, int sz) {
    asm volatile("cp.async.ca.shared.global [%0], [%1], 16, %2;"
                 :: "r"(dst), "l"(src), "r"(sz) : "memory");
}

__global__ void __launch_bounds__(256, 2)
mma_gemm(const __half* __restrict__ Ahi, const __half* __restrict__ Alo,
         const __half* __restrict__ Bh,
         float* __restrict__ C, const float* __restrict__ R, int N, int K) {
    extern __shared__ char dsm[];
    const int tid  = threadIdx.x;
    const int lane = tid & 31;
    const int wid  = tid >> 5;
    const int wm   = wid >> 2;
    const int wn   = wid & 3;
    const int m0 = blockIdx.x * 128;
    const int n0 = blockIdx.y * 128;
    const uint32_t sb = smem_u32(dsm);

    const int crow = tid >> 2;      // rows crow, crow+64
    const int cseg = tid & 3;

    const int rowA = wm * 64 + (lane & 15);
    const int offA = rowA * SPADB + (lane >> 4) * 16;
    const int rowB = wn * 32 + (lane & 7) + ((lane & 16) >> 1);
    const int offB = rowB * SPADB + (lane & 8) * 2;

    float acc[4][4][4];
    #pragma unroll
    for (int i = 0; i < 4; i++)
        #pragma unroll
        for (int j = 0; j < 4; j++)
            #pragma unroll
            for (int q = 0; q < 4; q++) acc[i][j][q] = 0.f;

    const int NCH = K >> 5;

    auto issue = [&](int c) {
        int k0 = c * 32;
        uint32_t st = sb + (c % NSTAGE) * STG_BYTES;
        #pragma unroll
        for (int p = 0; p < 2; p++) {
            int row = crow + p * 64;
            uint32_t so = (uint32_t)(row * SPADB + cseg * 16);
            size_t gk = (size_t)k0 + cseg * 8;
            cpa16(st + so,         Ahi + (size_t)(m0 + row) * K + gk, 16);
            cpa16(st + STG_M + so, Alo + (size_t)(m0 + row) * K + gk, 16);
            int nb = n0 + row;
            int sz = (nb < N) ? 16 : 0;
            int nbc = (nb < N) ? nb : (N - 1);
            cpa16(st + 2 * STG_M + so, Bh + (size_t)nbc * K + gk, sz);
        }
    };

    issue(0);
    asm volatile("cp.async.commit_group;" ::: "memory");
    issue(1);
    asm volatile("cp.async.commit_group;" ::: "memory");

    for (int c = 0; c < NCH; c++) {
        asm volatile("cp.async.wait_group 1;" ::: "memory");
        __syncthreads();
        if (c + 2 < NCH) issue(c + 2);
        asm volatile("cp.async.commit_group;" ::: "memory");

        uint32_t st = sb + (c % NSTAGE) * STG_BYTES;
        #pragma unroll
        for (int ks = 0; ks < 2; ks++) {
            uint32_t ah[4][4], al[4][4], bh[4][2];
            #pragma unroll
            for (int mt = 0; mt < 4; mt++) {
                uint32_t o = st + offA + mt * 16 * SPADB + ks * 32;
                LDSM4(ah[mt][0], ah[mt][1], ah[mt][2], ah[mt][3], o);
                LDSM4(al[mt][0], al[mt][1], al[mt][2], al[mt][3], o + STG_M);
            }
            #pragma unroll
            for (int np = 0; np < 2; np++) {
                uint32_t o = st + 2 * STG_M + offB + np * 16 * SPADB + ks * 32;
                uint32_t r0, r1, r2, r3;
                LDSM4(r0, r1, r2, r3, o);
                bh[np * 2][0] = r0; bh[np * 2][1] = r1;
                bh[np * 2 + 1][0] = r2; bh[np * 2 + 1][1] = r3;
            }
            #pragma unroll
            for (int mt = 0; mt < 4; mt++)
                #pragma unroll
                for (int nt = 0; nt < 4; nt++) {
                    MMA16816(acc[mt][nt], ah[mt], bh[nt]);
                    MMA16816(acc[mt][nt], al[mt], bh[nt]);
                }
        }
    }

    // epilogue
    #pragma unroll
    for (int mt = 0; mt < 4; mt++) {
        int row = m0 + wm * 64 + mt * 16 + (lane >> 2);
        #pragma unroll
        for (int nt = 0; nt < 4; nt++) {
            int col = n0 + wn * 32 + nt * 8 + (lane & 3) * 2;
            if (col < N) {
                size_t o0 = (size_t)row * N + col;
                size_t o1 = (size_t)(row + 8) * N + col;
                float2 v0 = make_float2(acc[mt][nt][0], acc[mt][nt][1]);
                float2 v1 = make_float2(acc[mt][nt][2], acc[mt][nt][3]);
                if (R) {
                    float2 r0 = *(const float2*)(R + o0);
                    float2 r1 = *(const float2*)(R + o1);
                    v0.x += r0.x; v0.y += r0.y;
                    v1.x += r1.x; v1.y += r1.y;
                }
                *(float2*)(C + o0) = v0;
                *(float2*)(C + o1) = v1;
            }
        }
    }
}

// ================= host orchestration ======================================
extern "C" void kernel_launch(void* const* d_in, const int* in_sizes, int n_in,
                              void* d_out, int out_size) {
    (void)in_sizes; (void)n_in; (void)out_size;
    const int*   input_ids = (const int*)  d_in[0];
    const float* emb       = (const float*)d_in[1];
    const float* in_proj_w = (const float*)d_in[2];
    const float* conv_w    = (const float*)d_in[3];
    const float* conv_b    = (const float*)d_in[4];
    const float* x_proj_w  = (const float*)d_in[5];
    const float* dt_proj_w = (const float*)d_in[6];
    const float* dt_proj_b = (const float*)d_in[7];
    const float* A_log     = (const float*)d_in[8];
    const float* D_param   = (const float*)d_in[9];
    const float* out_proj_w= (const float*)d_in[10];
    const float* norm_w    = (const float*)d_in[11];
    const float* norm_f_w  = (const float*)d_in[12];
    float* logits = (float*)d_out;

    float *px, *pxz, *pxi, *pxdbl, *pdelta;
    __half *pemb16, *pinw16, *pxpw16, *poutw16, *pacth, *pactl;
    cudaGetSymbolAddress((void**)&px,      g_x);
    cudaGetSymbolAddress((void**)&pxz,     g_xz);
    cudaGetSymbolAddress((void**)&pxi,     g_xi);
    cudaGetSymbolAddress((void**)&pxdbl,   g_xdbl);
    cudaGetSymbolAddress((void**)&pdelta,  g_delta);
    cudaGetSymbolAddress((void**)&pemb16,  g_emb16);
    cudaGetSymbolAddress((void**)&pinw16,  g_inw16);
    cudaGetSymbolAddress((void**)&pxpw16,  g_xpw16);
    cudaGetSymbolAddress((void**)&poutw16, g_outw16);
    cudaGetSymbolAddress((void**)&pacth,   g_acth);
    cudaGetSymbolAddress((void**)&pactl,   g_actl);

    cudaFuncSetAttribute(mma_gemm, cudaFuncAttributeMaxDynamicSharedMemorySize, GSMEM);

    // weight fp16 rounding (once per launch)
    {
        int n4 = NVOCAB * DM / 4;
        round_kernel<<<(n4 + 255) / 256, 256>>>(emb, pemb16, n4);
        n4 = NLAYER * 2 * DI * DM / 4;
        round_kernel<<<(n4 + 255) / 256, 256>>>(in_proj_w, pinw16, n4);
        n4 = NLAYER * 80 * DI / 4;
        round_kernel<<<(n4 + 255) / 256, 256>>>(x_proj_w, pxpw16, n4);
        n4 = NLAYER * DM * DI / 4;
        round_kernel<<<(n4 + 255) / 256, 256>>>(out_proj_w, poutw16, n4);
    }

    embed_kernel<<<SEQ, 256>>>(input_ids, emb, px);

    for (int i = 0; i < NLAYER; i++) {
        rmsnorm_split_kernel<<<SEQ, 256>>>(px, norm_w + (size_t)i * DM, pacth, pactl);
        // in_proj: (2048,768) x (3072,768)^T
        mma_gemm<<<dim3(SEQ / 128, 2 * DI / 128), 256, GSMEM>>>(
            pacth, pactl, pinw16 + (size_t)i * 2 * DI * DM,
            pxz, nullptr, 2 * DI, DM);
        conv_silu_kernel<<<(SEQ * DI + 255) / 256, 256>>>(
            pxz, conv_w + (size_t)i * DI * 4, conv_b + (size_t)i * DI,
            pxi, pacth, pactl);
        // x_proj: (2048,1536) x (80,1536)^T
        mma_gemm<<<dim3(SEQ / 128, 1), 256, GSMEM>>>(
            pacth, pactl, pxpw16 + (size_t)i * 80 * DI,
            pxdbl, nullptr, 80, DI);
        dtproj_kernel<<<dim3(DI / 128, SEQ / 16), 128>>>(
            pxdbl, dt_proj_w + (size_t)i * DI * DTR, dt_proj_b + (size_t)i * DI, pdelta);
        scan_kernel<<<DI / 8, 128>>>(
            pxdbl, pdelta, pxi, pxz,
            A_log + (size_t)i * DI * DS, D_param + (size_t)i * DI, pacth, pactl);
        // out_proj + residual
        mma_gemm<<<dim3(SEQ / 128, DM / 128), 256, GSMEM>>>(
            pacth, pactl, poutw16 + (size_t)i * DM * DI,
            px, px, DM, DI);
    }

    rmsnorm_split_kernel<<<SEQ, 256>>>(px, norm_f_w, pacth, pactl);
    // logits: (2048,768) x (50264,768)^T
    mma_gemm<<<dim3(SEQ / 128, (NVOCAB + 127) / 128), 256, GSMEM>>>(
        pacth, pactl, pemb16, logits, nullptr, NVOCAB, DM);
}

// round 11
// speedup vs baseline: 1.1181x; 1.0455x over previous
#include <cuda_runtime.h>
#include <cuda_fp16.h>
#include <math.h>
#include <stdint.h>

#define SEQ    2048
#define DM     768
#define DI     1536
#define DS     16
#define DTR    48
#define NLAYER 4
#define NVOCAB 50264

// ---------------- fp32 scratch ----------------
__device__ float g_x   [SEQ * DM];
__device__ float g_xz  [SEQ * 2 * DI];
__device__ float g_xi  [SEQ * DI];
__device__ float g_xdbl[SEQ * 80];
__device__ float g_delta[SEQ * DI];

// ---------------- fp16 scratch ----------------
__device__ __half g_emb16 [NVOCAB * DM];
__device__ __half g_inw16 [NLAYER * 2 * DI * DM];
__device__ __half g_xpw16 [NLAYER * 80 * DI];
__device__ __half g_outw16[NLAYER * DM * DI];
__device__ __half g_acth  [SEQ * DI];
__device__ __half g_actl  [SEQ * DI];

__device__ __forceinline__ void split1h(float v, __half& h, __half& l) {
    h = __float2half_rn(v);
    l = __float2half_rn(v - __half2float(h));
}
__device__ __forceinline__ uint32_t smem_u32(const void* p) {
    uint32_t a;
    asm("{ .reg .u64 t; cvta.to.shared.u64 t, %1; cvt.u32.u64 %0, t; }"
        : "=r"(a) : "l"(p));
    return a;
}

// ---------------- weight fp32 -> fp16 round ----------------
__global__ void round_kernel(const float* __restrict__ x,
                             __half* __restrict__ o, int n4) {
    int i = blockIdx.x * blockDim.x + threadIdx.x;
    if (i >= n4) return;
    float4 v = ((const float4*)x)[i];
    __half2 h01 = __floats2half2_rn(v.x, v.y);
    __half2 h23 = __floats2half2_rn(v.z, v.w);
    ((uint2*)o)[i] = make_uint2(*(uint32_t*)&h01, *(uint32_t*)&h23);
}

// ---------------- zero fill ----------------
__global__ void zero_kernel(float* __restrict__ p, int n) {
    int i = blockIdx.x * blockDim.x + threadIdx.x;
    if (i < n) p[i] = 0.f;
}

// ---------------- embedding gather ----------------
__global__ void embed_kernel(const int* __restrict__ ids,
                             const float* __restrict__ emb,
                             float* __restrict__ x) {
    int t = blockIdx.x;
    int id = ids[t];
    const float* src = emb + (size_t)id * DM;
    float* dst = x + (size_t)t * DM;
    for (int c = threadIdx.x; c < DM; c += 256) dst[c] = src[c];
}

// ---------------- rmsnorm with fp16 split output ----------------
__global__ void rmsnorm_split_kernel(const float* __restrict__ x,
                                     const float* __restrict__ w,
                                     __half* __restrict__ ohi,
                                     __half* __restrict__ olo) {
    int row = blockIdx.x;
    const float* xr = x + (size_t)row * DM;
    float ss = 0.f;
    for (int c = threadIdx.x; c < DM; c += 256) { float v = xr[c]; ss += v * v; }
    #pragma unroll
    for (int o = 16; o; o >>= 1) ss += __shfl_xor_sync(0xffffffffu, ss, o);
    __shared__ float sred[8];
    if ((threadIdx.x & 31) == 0) sred[threadIdx.x >> 5] = ss;
    __syncthreads();
    if (threadIdx.x < 8) {
        float v = sred[threadIdx.x];
        #pragma unroll
        for (int o = 4; o; o >>= 1) v += __shfl_xor_sync(0xffu, v, o);
        if (threadIdx.x == 0) sred[0] = v;
    }
    __syncthreads();
    float scale = rsqrtf(sred[0] / (float)DM + 1e-5f);
    for (int c = threadIdx.x; c < DM; c += 256) {
        float v = xr[c] * scale * w[c];
        __half h, l;
        split1h(v, h, l);
        ohi[(size_t)row * DM + c] = h;
        olo[(size_t)row * DM + c] = l;
    }
}

// ---------------- conv + silu, fp32 + fp16 split outputs ----------------
__global__ void conv_silu_kernel(const float* __restrict__ xz,
                                 const float* __restrict__ cw,
                                 const float* __restrict__ cb,
                                 float* __restrict__ xi,
                                 __half* __restrict__ ohi,
                                 __half* __restrict__ olo) {
    int idx = blockIdx.x * blockDim.x + threadIdx.x;
    if (idx >= SEQ * DI) return;
    int t = idx / DI;
    int d = idx - t * DI;
    float acc = cb[d];
    #pragma unroll
    for (int k = 0; k < 4; k++) {
        int tt = t - 3 + k;
        if (tt >= 0) acc = fmaf(xz[(size_t)tt * (2 * DI) + d], cw[d * 4 + k], acc);
    }
    float v = acc / (1.f + __expf(-acc));
    xi[idx] = v;
    __half h, l;
    split1h(v, h, l);
    ohi[idx] = h;
    olo[idx] = l;
}

// ---------------- dt_proj (K=48) + softplus ----------------
__global__ void __launch_bounds__(128)
dtproj_kernel(const float* __restrict__ xdbl, const float* __restrict__ W,
              const float* __restrict__ b, float* __restrict__ delta) {
    int d = blockIdx.x * 128 + threadIdx.x;
    int t0 = blockIdx.y * 16;
    __shared__ float sx[16][DTR];
    for (int i = threadIdx.x; i < 16 * DTR; i += 128) {
        int tt = i / DTR, r = i - tt * DTR;
        sx[tt][r] = xdbl[(size_t)(t0 + tt) * 80 + r];
    }
    float w[DTR];
    #pragma unroll
    for (int r = 0; r < DTR; r++) w[r] = W[(size_t)d * DTR + r];
    float bias = b[d];
    __syncthreads();
    for (int tt = 0; tt < 16; tt++) {
        float acc = bias;
        #pragma unroll
        for (int r = 0; r < DTR; r++) acc = fmaf(sx[tt][r], w[r], acc);
        float sp = fmaxf(acc, 0.f) + log1pf(__expf(-fabsf(acc)));
        delta[(size_t)(t0 + tt) * DI + d] = sp;
    }
}

// ---------------- selective scan + gating, fp16 split output ----------------
#define SCAN_T 64
__global__ void __launch_bounds__(128)
scan_kernel(const float* __restrict__ xdbl, const float* __restrict__ delta,
            const float* __restrict__ xi, const float* __restrict__ xz,
            const float* __restrict__ A_log, const float* __restrict__ Dp,
            __half* __restrict__ yhi, __half* __restrict__ ylo) {
    __shared__ float sB[SCAN_T][16];
    __shared__ float sC[SCAN_T][16];
    __shared__ float sDt[SCAN_T][8];
    __shared__ float sU[SCAN_T][8];
    __shared__ float sRes[SCAN_T][8];
    __shared__ float sY[SCAN_T][8];

    int tid = threadIdx.x;
    int lane = tid & 31;
    int warp = tid >> 5;
    int ch = (warp << 1) | (lane >> 4);
    int n = lane & 15;
    int d0 = blockIdx.x * 8;
    int d = d0 + ch;

    float a = -__expf(A_log[(size_t)d * DS + n]);
    float Dv = Dp[d];
    float h = 0.f;

    for (int t0 = 0; t0 < SEQ; t0 += SCAN_T) {
        for (int i = tid; i < SCAN_T * 16; i += 128) {
            int tt = i >> 4, j = i & 15;
            size_t base = (size_t)(t0 + tt) * 80;
            sB[tt][j] = xdbl[base + DTR + j];
            sC[tt][j] = xdbl[base + DTR + DS + j];
        }
        for (int i = tid; i < SCAN_T * 8; i += 128) {
            int tt = i >> 3, j = i & 7;
            sDt[tt][j]  = delta[(size_t)(t0 + tt) * DI + d0 + j];
            sU[tt][j]   = xi[(size_t)(t0 + tt) * DI + d0 + j];
            sRes[tt][j] = xz[(size_t)(t0 + tt) * (2 * DI) + DI + d0 + j];
        }
        __syncthreads();
        #pragma unroll 4
        for (int tt = 0; tt < SCAN_T; tt++) {
            float dt = sDt[tt][ch];
            float u  = sU[tt][ch];
            float Bt = sB[tt][n];
            float Ct = sC[tt][n];
            float dA = __expf(dt * a);
            h = fmaf(dA, h, dt * Bt * u);
            float p = h * Ct;
            p += __shfl_xor_sync(0xffffffffu, p, 1);
            p += __shfl_xor_sync(0xffffffffu, p, 2);
            p += __shfl_xor_sync(0xffffffffu, p, 4);
            p += __shfl_xor_sync(0xffffffffu, p, 8);
            if (n == 0) {
                float res = sRes[tt][ch];
                float g = res / (1.f + __expf(-res));
                sY[tt][ch] = (p + u * Dv) * g;
            }
        }
        __syncthreads();
        for (int i = tid; i < SCAN_T * 8; i += 128) {
            int tt = i >> 3, j = i & 7;
            float v = sY[tt][j];
            __half hh, ll;
            split1h(v, hh, ll);
            size_t o = (size_t)(t0 + tt) * DI + d0 + j;
            yhi[o] = hh;
            ylo[o] = ll;
        }
        __syncthreads();
    }
}

// ================= HMMA fp16 2-term GEMM with optional split-K =============
// C[M,N] = (Ahi+Alo)[M,K] @ Bh[N,K]^T (+R).
// BM=BN=128, BK=32, 256 thr, 8 warps (2x4), warp tile 64x32.
// blockIdx.z slices K; gridDim.z>1 -> atomic fp32 accumulate into C.
#define SPADB  80
#define STG_M  (128 * SPADB)
#define STG_BYTES (3 * STG_M)
#define NSTAGE 3
#define GSMEM  (NSTAGE * STG_BYTES) // 92160; x2 CTAs = 184320 < 227KB

#define LDSM4(r0, r1, r2, r3, addr) \
    asm volatile("ldmatrix.sync.aligned.m8n8.x4.shared.b16 {%0,%1,%2,%3}, [%4];" \
        : "=r"(r0), "=r"(r1), "=r"(r2), "=r"(r3) : "r"(addr))

#define MMA16816(c, a, b) \
    asm volatile("mma.sync.aligned.m16n8k16.row.col.f32.f16.f16.f32 " \
        "{%0,%1,%2,%3},{%4,%5,%6,%7},{%8,%9},{%0,%1,%2,%3};" \
        : "+f"((c)[0]), "+f"((c)[1]), "+f"((c)[2]), "+f"((c)[3]) \
        : "r"((a)[0]), "r"((a)[1]), "r"((a)[2]), "r"((a)[3]), \
          "r"((b)[0]), "r"((b)[1]))

__device__ __forceinline__ void cpa16(uint32_t dst, const void* src, int sz) {
    asm volatile("cp.async.ca.shared.global [%0], [%1], 16, %2;"
                 :: "r"(dst), "l"(src), "r"(sz) : "memory");
}

__global__ void __launch_bounds__(256, 2)
mma_gemm(const __half* __restrict__ Ahi, const __half* __restrict__ Alo,
         const __half* __restrict__ Bh,
         float* __restrict__ C, const float* __restrict__ R, int N, int K) {
    extern __shared__ char dsm[];
    const int tid  = threadIdx.x;
    const int lane = tid & 31;
    const int wid  = tid >> 5;
    const int wm   = wid >> 2;
    const int wn   = wid & 3;
    const int m0 = blockIdx.x * 128;
    const int n0 = blockIdx.y * 128;
    const uint32_t sb = smem_u32(dsm);

    const int ksl   = K / gridDim.z;          // K slice per CTA
    const int kbase = blockIdx.z * ksl;
    const int NCH   = ksl >> 5;

    const int crow = tid >> 2;      // rows crow, crow+64
    const int cseg = tid & 3;

    const int rowA = wm * 64 + (lane & 15);
    const int offA = rowA * SPADB + (lane >> 4) * 16;
    const int rowB = wn * 32 + (lane & 7) + ((lane & 16) >> 1);
    const int offB = rowB * SPADB + (lane & 8) * 2;

    float acc[4][4][4];
    #pragma unroll
    for (int i = 0; i < 4; i++)
        #pragma unroll
        for (int j = 0; j < 4; j++)
            #pragma unroll
            for (int q = 0; q < 4; q++) acc[i][j][q] = 0.f;

    auto issue = [&](int c) {
        int k0 = kbase + c * 32;
        uint32_t st = sb + (c % NSTAGE) * STG_BYTES;
        #pragma unroll
        for (int p = 0; p < 2; p++) {
            int row = crow + p * 64;
            uint32_t so = (uint32_t)(row * SPADB + cseg * 16);
            size_t gk = (size_t)k0 + cseg * 8;
            cpa16(st + so,         Ahi + (size_t)(m0 + row) * K + gk, 16);
            cpa16(st + STG_M + so, Alo + (size_t)(m0 + row) * K + gk, 16);
            int nb = n0 + row;
            int sz = (nb < N) ? 16 : 0;
            int nbc = (nb < N) ? nb : (N - 1);
            cpa16(st + 2 * STG_M + so, Bh + (size_t)nbc * K + gk, sz);
        }
    };

    issue(0);
    asm volatile("cp.async.commit_group;" ::: "memory");
    issue(1);
    asm volatile("cp.async.commit_group;" ::: "memory");

    for (int c = 0; c < NCH; c++) {
        asm volatile("cp.async.wait_group 1;" ::: "memory");
        __syncthreads();
        if (c + 2 < NCH) issue(c + 2);
        asm volatile("cp.async.commit_group;" ::: "memory");

        uint32_t st = sb + (c % NSTAGE) * STG_BYTES;
        #pragma unroll
        for (int ks = 0; ks < 2; ks++) {
            uint32_t ah[4][4], al[4][4], bh[4][2];
            #pragma unroll
            for (int mt = 0; mt < 4; mt++) {
                uint32_t o = st + offA + mt * 16 * SPADB + ks * 32;
                LDSM4(ah[mt][0], ah[mt][1], ah[mt][2], ah[mt][3], o);
                LDSM4(al[mt][0], al[mt][1], al[mt][2], al[mt][3], o + STG_M);
            }
            #pragma unroll
            for (int np = 0; np < 2; np++) {
                uint32_t o = st + 2 * STG_M + offB + np * 16 * SPADB + ks * 32;
                uint32_t r0, r1, r2, r3;
                LDSM4(r0, r1, r2, r3, o);
                bh[np * 2][0] = r0; bh[np * 2][1] = r1;
                bh[np * 2 + 1][0] = r2; bh[np * 2 + 1][1] = r3;
            }
            #pragma unroll
            for (int mt = 0; mt < 4; mt++)
                #pragma unroll
                for (int nt = 0; nt < 4; nt++) {
                    MMA16816(acc[mt][nt], ah[mt], bh[nt]);
                    MMA16816(acc[mt][nt], al[mt], bh[nt]);
                }
        }
    }

    // epilogue: normal store (+R) or atomic accumulate for split-K
    const bool atom = (gridDim.z > 1);
    #pragma unroll
    for (int mt = 0; mt < 4; mt++) {
        int row = m0 + wm * 64 + mt * 16 + (lane >> 2);
        #pragma unroll
        for (int nt = 0; nt < 4; nt++) {
            int col = n0 + wn * 32 + nt * 8 + (lane & 3) * 2;
            if (col < N) {
                size_t o0 = (size_t)row * N + col;
                size_t o1 = (size_t)(row + 8) * N + col;
                float2 v0 = make_float2(acc[mt][nt][0], acc[mt][nt][1]);
                float2 v1 = make_float2(acc[mt][nt][2], acc[mt][nt][3]);
                if (atom) {
                    atomicAdd((float2*)(C + o0), v0);
                    atomicAdd((float2*)(C + o1), v1);
                } else {
                    if (R) {
                        float2 r0 = *(const float2*)(R + o0);
                        float2 r1 = *(const float2*)(R + o1);
                        v0.x += r0.x; v0.y += r0.y;
                        v1.x += r1.x; v1.y += r1.y;
                    }
                    *(float2*)(C + o0) = v0;
                    *(float2*)(C + o1) = v1;
                }
            }
        }
    }
}

// ================= host orchestration ======================================
extern "C" void kernel_launch(void* const* d_in, const int* in_sizes, int n_in,
                              void* d_out, int out_size) {
    (void)in_sizes; (void)n_in; (void)out_size;
    const int*   input_ids = (const int*)  d_in[0];
    const float* emb       = (const float*)d_in[1];
    const float* in_proj_w = (const float*)d_in[2];
    const float* conv_w    = (const float*)d_in[3];
    const float* conv_b    = (const float*)d_in[4];
    const float* x_proj_w  = (const float*)d_in[5];
    const float* dt_proj_w = (const float*)d_in[6];
    const float* dt_proj_b = (const float*)d_in[7];
    const float* A_log     = (const float*)d_in[8];
    const float* D_param   = (const float*)d_in[9];
    const float* out_proj_w= (const float*)d_in[10];
    const float* norm_w    = (const float*)d_in[11];
    const float* norm_f_w  = (const float*)d_in[12];
    float* logits = (float*)d_out;

    float *px, *pxz, *pxi, *pxdbl, *pdelta;
    __half *pemb16, *pinw16, *pxpw16, *poutw16, *pacth, *pactl;
    cudaGetSymbolAddress((void**)&px,      g_x);
    cudaGetSymbolAddress((void**)&pxz,     g_xz);
    cudaGetSymbolAddress((void**)&pxi,     g_xi);
    cudaGetSymbolAddress((void**)&pxdbl,   g_xdbl);
    cudaGetSymbolAddress((void**)&pdelta,  g_delta);
    cudaGetSymbolAddress((void**)&pemb16,  g_emb16);
    cudaGetSymbolAddress((void**)&pinw16,  g_inw16);
    cudaGetSymbolAddress((void**)&pxpw16,  g_xpw16);
    cudaGetSymbolAddress((void**)&poutw16, g_outw16);
    cudaGetSymbolAddress((void**)&pacth,   g_acth);
    cudaGetSymbolAddress((void**)&pactl,   g_actl);

    cudaFuncSetAttribute(mma_gemm, cudaFuncAttributeMaxDynamicSharedMemorySize, GSMEM);

    // weight fp16 rounding (once per launch)
    {
        int n4 = NVOCAB * DM / 4;
        round_kernel<<<(n4 + 255) / 256, 256>>>(emb, pemb16, n4);
        n4 = NLAYER * 2 * DI * DM / 4;
        round_kernel<<<(n4 + 255) / 256, 256>>>(in_proj_w, pinw16, n4);
        n4 = NLAYER * 80 * DI / 4;
        round_kernel<<<(n4 + 255) / 256, 256>>>(x_proj_w, pxpw16, n4);
        n4 = NLAYER * DM * DI / 4;
        round_kernel<<<(n4 + 255) / 256, 256>>>(out_proj_w, poutw16, n4);
    }

    embed_kernel<<<SEQ, 256>>>(input_ids, emb, px);

    for (int i = 0; i < NLAYER; i++) {
        rmsnorm_split_kernel<<<SEQ, 256>>>(px, norm_w + (size_t)i * DM, pacth, pactl);
        // in_proj: (2048,768) x (3072,768)^T
        mma_gemm<<<dim3(SEQ / 128, 2 * DI / 128), 256, GSMEM>>>(
            pacth, pactl, pinw16 + (size_t)i * 2 * DI * DM,
            pxz, nullptr, 2 * DI, DM);
        conv_silu_kernel<<<(SEQ * DI + 255) / 256, 256>>>(
            pxz, conv_w + (size_t)i * DI * 4, conv_b + (size_t)i * DI,
            pxi, pacth, pactl);
        // x_proj: (2048,1536) x (80,1536)^T  — split-K=16, atomic accumulate
        zero_kernel<<<(SEQ * 80 + 255) / 256, 256>>>(pxdbl, SEQ * 80);
        mma_gemm<<<dim3(SEQ / 128, 1, 16), 256, GSMEM>>>(
            pacth, pactl, pxpw16 + (size_t)i * 80 * DI,
            pxdbl, nullptr, 80, DI);
        dtproj_kernel<<<dim3(DI / 128, SEQ / 16), 128>>>(
            pxdbl, dt_proj_w + (size_t)i * DI * DTR, dt_proj_b + (size_t)i * DI, pdelta);
        scan_kernel<<<DI / 8, 128>>>(
            pxdbl, pdelta, pxi, pxz,
            A_log + (size_t)i * DI * DS, D_param + (size_t)i * DI, pacth, pactl);
        // out_proj + residual: split-K=4, atomic accumulate into px (residual resident)
        mma_gemm<<<dim3(SEQ / 128, DM / 128, 4), 256, GSMEM>>>(
            pacth, pactl, poutw16 + (size_t)i * DM * DI,
            px, nullptr, DM, DI);
    }

    rmsnorm_split_kernel<<<SEQ, 256>>>(px, norm_f_w, pacth, pactl);
    // logits: (2048,768) x (50264,768)^T
    mma_gemm<<<dim3(SEQ / 128, (NVOCAB + 127) / 128), 256, GSMEM>>>(
        pacth, pactl, pemb16, logits, nullptr, NVOCAB, DM);
}

// round 13
// speedup vs baseline: 1.1548x; 1.0328x over previous
#include <cuda_runtime.h>
#include <cuda_fp16.h>
#include <math.h>
#include <stdint.h>

#define SEQ    2048
#define DM     768
#define DI     1536
#define DS     16
#define DTR    48
#define NLAYER 4
#define NVOCAB 50264

// ---------------- fp32 scratch ----------------
__device__ float g_x   [SEQ * DM];
__device__ float g_xz  [SEQ * 2 * DI];
__device__ float g_xi  [SEQ * DI];
__device__ float g_xdbl[SEQ * 80];
__device__ float g_delta[SEQ * DI];

// ---------------- fp16 scratch ----------------
__device__ __half g_emb16 [NVOCAB * DM];
__device__ __half g_inw16 [NLAYER * 2 * DI * DM];
__device__ __half g_xpw16 [NLAYER * 80 * DI];
__device__ __half g_outw16[NLAYER * DM * DI];
__device__ __half g_acth  [SEQ * DI];
__device__ __half g_actl  [SEQ * DI];

__device__ __forceinline__ void split1h(float v, __half& h, __half& l) {
    h = __float2half_rn(v);
    l = __float2half_rn(v - __half2float(h));
}
__device__ __forceinline__ uint32_t smem_u32(const void* p) {
    uint32_t a;
    asm("{ .reg .u64 t; cvta.to.shared.u64 t, %1; cvt.u32.u64 %0, t; }"
        : "=r"(a) : "l"(p));
    return a;
}

// ---------------- weight fp32 -> fp16 round ----------------
__global__ void round_kernel(const float* __restrict__ x,
                             __half* __restrict__ o, int n4) {
    int i = blockIdx.x * blockDim.x + threadIdx.x;
    if (i >= n4) return;
    float4 v = ((const float4*)x)[i];
    __half2 h01 = __floats2half2_rn(v.x, v.y);
    __half2 h23 = __floats2half2_rn(v.z, v.w);
    ((uint2*)o)[i] = make_uint2(*(uint32_t*)&h01, *(uint32_t*)&h23);
}

// ---------------- zero fill ----------------
__global__ void zero_kernel(float* __restrict__ p, int n) {
    int i = blockIdx.x * blockDim.x + threadIdx.x;
    if (i < n) p[i] = 0.f;
}

// ---------------- embedding gather ----------------
__global__ void embed_kernel(const int* __restrict__ ids,
                             const float* __restrict__ emb,
                             float* __restrict__ x) {
    int t = blockIdx.x;
    int id = ids[t];
    const float* src = emb + (size_t)id * DM;
    float* dst = x + (size_t)t * DM;
    for (int c = threadIdx.x; c < DM; c += 256) dst[c] = src[c];
}

// ---------------- rmsnorm with fp16 split output ----------------
__global__ void rmsnorm_split_kernel(const float* __restrict__ x,
                                     const float* __restrict__ w,
                                     __half* __restrict__ ohi,
                                     __half* __restrict__ olo) {
    int row = blockIdx.x;
    const float* xr = x + (size_t)row * DM;
    float ss = 0.f;
    for (int c = threadIdx.x; c < DM; c += 256) { float v = xr[c]; ss += v * v; }
    #pragma unroll
    for (int o = 16; o; o >>= 1) ss += __shfl_xor_sync(0xffffffffu, ss, o);
    __shared__ float sred[8];
    if ((threadIdx.x & 31) == 0) sred[threadIdx.x >> 5] = ss;
    __syncthreads();
    if (threadIdx.x < 8) {
        float v = sred[threadIdx.x];
        #pragma unroll
        for (int o = 4; o; o >>= 1) v += __shfl_xor_sync(0xffu, v, o);
        if (threadIdx.x == 0) sred[0] = v;
    }
    __syncthreads();
    float scale = rsqrtf(sred[0] / (float)DM + 1e-5f);
    for (int c = threadIdx.x; c < DM; c += 256) {
        float v = xr[c] * scale * w[c];
        __half h, l;
        split1h(v, h, l);
        ohi[(size_t)row * DM + c] = h;
        olo[(size_t)row * DM + c] = l;
    }
}

// ---------------- conv + silu, fp32 + fp16 split outputs ----------------
__global__ void conv_silu_kernel(const float* __restrict__ xz,
                                 const float* __restrict__ cw,
                                 const float* __restrict__ cb,
                                 float* __restrict__ xi,
                                 __half* __restrict__ ohi,
                                 __half* __restrict__ olo) {
    int idx = blockIdx.x * blockDim.x + threadIdx.x;
    if (idx >= SEQ * DI) return;
    int t = idx / DI;
    int d = idx - t * DI;
    float acc = cb[d];
    #pragma unroll
    for (int k = 0; k < 4; k++) {
        int tt = t - 3 + k;
        if (tt >= 0) acc = fmaf(xz[(size_t)tt * (2 * DI) + d], cw[d * 4 + k], acc);
    }
    float v = acc / (1.f + __expf(-acc));
    xi[idx] = v;
    __half h, l;
    split1h(v, h, l);
    ohi[idx] = h;
    olo[idx] = l;
}

// ---------------- dt_proj (K=48) + softplus ----------------
__global__ void __launch_bounds__(128)
dtproj_kernel(const float* __restrict__ xdbl, const float* __restrict__ W,
              const float* __restrict__ b, float* __restrict__ delta) {
    int d = blockIdx.x * 128 + threadIdx.x;
    int t0 = blockIdx.y * 16;
    __shared__ float sx[16][DTR];
    for (int i = threadIdx.x; i < 16 * DTR; i += 128) {
        int tt = i / DTR, r = i - tt * DTR;
        sx[tt][r] = xdbl[(size_t)(t0 + tt) * 80 + r];
    }
    float w[DTR];
    #pragma unroll
    for (int r = 0; r < DTR; r++) w[r] = W[(size_t)d * DTR + r];
    float bias = b[d];
    __syncthreads();
    for (int tt = 0; tt < 16; tt++) {
        float acc = bias;
        #pragma unroll
        for (int r = 0; r < DTR; r++) acc = fmaf(sx[tt][r], w[r], acc);
        float sp = fmaxf(acc, 0.f) + log1pf(__expf(-fabsf(acc)));
        delta[(size_t)(t0 + tt) * DI + d] = sp;
    }
}

// ---------------- selective scan + gating, fp16 split output ----------------
#define SCAN_T 64
__global__ void __launch_bounds__(128)
scan_kernel(const float* __restrict__ xdbl, const float* __restrict__ delta,
            const float* __restrict__ xi, const float* __restrict__ xz,
            const float* __restrict__ A_log, const float* __restrict__ Dp,
            __half* __restrict__ yhi, __half* __restrict__ ylo) {
    __shared__ float sB[SCAN_T][16];
    __shared__ float sC[SCAN_T][16];
    __shared__ float sDt[SCAN_T][8];
    __shared__ float sU[SCAN_T][8];
    __shared__ float sRes[SCAN_T][8];
    __shared__ float sY[SCAN_T][8];

    int tid = threadIdx.x;
    int lane = tid & 31;
    int warp = tid >> 5;
    int ch = (warp << 1) | (lane >> 4);
    int n = lane & 15;
    int d0 = blockIdx.x * 8;
    int d = d0 + ch;

    float a = -__expf(A_log[(size_t)d * DS + n]);
    float Dv = Dp[d];
    float h = 0.f;

    for (int t0 = 0; t0 < SEQ; t0 += SCAN_T) {
        for (int i = tid; i < SCAN_T * 16; i += 128) {
            int tt = i >> 4, j = i & 15;
            size_t base = (size_t)(t0 + tt) * 80;
            sB[tt][j] = xdbl[base + DTR + j];
            sC[tt][j] = xdbl[base + DTR + DS + j];
        }
        for (int i = tid; i < SCAN_T * 8; i += 128) {
            int tt = i >> 3, j = i & 7;
            sDt[tt][j]  = delta[(size_t)(t0 + tt) * DI + d0 + j];
            sU[tt][j]   = xi[(size_t)(t0 + tt) * DI + d0 + j];
            sRes[tt][j] = xz[(size_t)(t0 + tt) * (2 * DI) + DI + d0 + j];
        }
        __syncthreads();
        #pragma unroll 4
        for (int tt = 0; tt < SCAN_T; tt++) {
            float dt = sDt[tt][ch];
            float u  = sU[tt][ch];
            float Bt = sB[tt][n];
            float Ct = sC[tt][n];
            float dA = __expf(dt * a);
            h = fmaf(dA, h, dt * Bt * u);
            float p = h * Ct;
            p += __shfl_xor_sync(0xffffffffu, p, 1);
            p += __shfl_xor_sync(0xffffffffu, p, 2);
            p += __shfl_xor_sync(0xffffffffu, p, 4);
            p += __shfl_xor_sync(0xffffffffu, p, 8);
            if (n == 0) {
                float res = sRes[tt][ch];
                float g = res / (1.f + __expf(-res));
                sY[tt][ch] = (p + u * Dv) * g;
            }
        }
        __syncthreads();
        for (int i = tid; i < SCAN_T * 8; i += 128) {
            int tt = i >> 3, j = i & 7;
            float v = sY[tt][j];
            __half hh, ll;
            split1h(v, hh, ll);
            size_t o = (size_t)(t0 + tt) * DI + d0 + j;
            yhi[o] = hh;
            ylo[o] = ll;
        }
        __syncthreads();
    }
}

// ================= HMMA fp16 GEMM: 2-term (Alo!=null) or 1-term ===========
// C[M,N] = (Ahi[+Alo])[M,K] @ Bh[N,K]^T (+R).
// BM=BN=128, BK=32, 256 thr, 8 warps (2x4), warp tile 64x32.
// blockIdx.z slices K; gridDim.z>1 -> atomic fp32 accumulate into C.
#define SPADB  80
#define STG_M  (128 * SPADB)
#define STG_BYTES (3 * STG_M)
#define NSTAGE 3
#define GSMEM  (NSTAGE * STG_BYTES) // 92160; x2 CTAs = 184320 < 227KB

#define LDSM4(r0, r1, r2, r3, addr) \
    asm volatile("ldmatrix.sync.aligned.m8n8.x4.shared.b16 {%0,%1,%2,%3}, [%4];" \
        : "=r"(r0), "=r"(r1), "=r"(r2), "=r"(r3) : "r"(addr))

#define MMA16816(c, a, b) \
    asm volatile("mma.sync.aligned.m16n8k16.row.col.f32.f16.f16.f32 " \
        "{%0,%1,%2,%3},{%4,%5,%6,%7},{%8,%9},{%0,%1,%2,%3};" \
        : "+f"((c)[0]), "+f"((c)[1]), "+f"((c)[2]), "+f"((c)[3]) \
        : "r"((a)[0]), "r"((a)[1]), "r"((a)[2]), "r"((a)[3]), \
          "r"((b)[0]), "r"((b)[1]))

__device__ __forceinline__ void cpa16(uint32_t dst, const void* src, int sz) {
    asm volatile("cp.async.ca.shared.global [%0], [%1], 16, %2;"
                 :: "r"(dst), "l"(src), "r"(sz) : "memory");
}

__global__ void __launch_bounds__(256, 2)
mma_gemm(const __half* __restrict__ Ahi, const __half* __restrict__ Alo,
         const __half* __restrict__ Bh,
         float* __restrict__ C, const float* __restrict__ R, int N, int K) {
    extern __shared__ char dsm[];
    const int tid  = threadIdx.x;
    const int lane = tid & 31;
    const int wid  = tid >> 5;
    const int wm   = wid >> 2;
    const int wn   = wid & 3;
    const int m0 = blockIdx.x * 128;
    const int n0 = blockIdx.y * 128;
    const uint32_t sb = smem_u32(dsm);
    const bool two = (Alo != nullptr);

    const int ksl   = K / gridDim.z;          // K slice per CTA
    const int kbase = blockIdx.z * ksl;
    const int NCH   = ksl >> 5;

    const int crow = tid >> 2;      // rows crow, crow+64
    const int cseg = tid & 3;

    const int rowA = wm * 64 + (lane & 15);
    const int offA = rowA * SPADB + (lane >> 4) * 16;
    const int rowB = wn * 32 + (lane & 7) + ((lane & 16) >> 1);
    const int offB = rowB * SPADB + (lane & 8) * 2;

    float acc[4][4][4];
    #pragma unroll
    for (int i = 0; i < 4; i++)
        #pragma unroll
        for (int j = 0; j < 4; j++)
            #pragma unroll
            for (int q = 0; q < 4; q++) acc[i][j][q] = 0.f;

    auto issue = [&](int c) {
        int k0 = kbase + c * 32;
        uint32_t st = sb + (c % NSTAGE) * STG_BYTES;
        #pragma unroll
        for (int p = 0; p < 2; p++) {
            int row = crow + p * 64;
            uint32_t so = (uint32_t)(row * SPADB + cseg * 16);
            size_t gk = (size_t)k0 + cseg * 8;
            cpa16(st + so, Ahi + (size_t)(m0 + row) * K + gk, 16);
            if (two)
                cpa16(st + STG_M + so, Alo + (size_t)(m0 + row) * K + gk, 16);
            int nb = n0 + row;
            int sz = (nb < N) ? 16 : 0;
            int nbc = (nb < N) ? nb : (N - 1);
            cpa16(st + 2 * STG_M + so, Bh + (size_t)nbc * K + gk, sz);
        }
    };

    issue(0);
    asm volatile("cp.async.commit_group;" ::: "memory");
    issue(1);
    asm volatile("cp.async.commit_group;" ::: "memory");

    for (int c = 0; c < NCH; c++) {
        asm volatile("cp.async.wait_group 1;" ::: "memory");
        __syncthreads();
        if (c + 2 < NCH) issue(c + 2);
        asm volatile("cp.async.commit_group;" ::: "memory");

        uint32_t st = sb + (c % NSTAGE) * STG_BYTES;
        #pragma unroll
        for (int ks = 0; ks < 2; ks++) {
            uint32_t ah[4][4], al[4][4], bh[4][2];
            #pragma unroll
            for (int mt = 0; mt < 4; mt++) {
                uint32_t o = st + offA + mt * 16 * SPADB + ks * 32;
                LDSM4(ah[mt][0], ah[mt][1], ah[mt][2], ah[mt][3], o);
                if (two)
                    LDSM4(al[mt][0], al[mt][1], al[mt][2], al[mt][3], o + STG_M);
            }
            #pragma unroll
            for (int np = 0; np < 2; np++) {
                uint32_t o = st + 2 * STG_M + offB + np * 16 * SPADB + ks * 32;
                uint32_t r0, r1, r2, r3;
                LDSM4(r0, r1, r2, r3, o);
                bh[np * 2][0] = r0; bh[np * 2][1] = r1;
                bh[np * 2 + 1][0] = r2; bh[np * 2 + 1][1] = r3;
            }
            #pragma unroll
            for (int mt = 0; mt < 4; mt++)
                #pragma unroll
                for (int nt = 0; nt < 4; nt++) {
                    MMA16816(acc[mt][nt], ah[mt], bh[nt]);
                    if (two) MMA16816(acc[mt][nt], al[mt], bh[nt]);
                }
        }
    }

    // epilogue: normal store (+R) or atomic accumulate for split-K
    const bool atom = (gridDim.z > 1);
    #pragma unroll
    for (int mt = 0; mt < 4; mt++) {
        int row = m0 + wm * 64 + mt * 16 + (lane >> 2);
        #pragma unroll
        for (int nt = 0; nt < 4; nt++) {
            int col = n0 + wn * 32 + nt * 8 + (lane & 3) * 2;
            if (col < N) {
                size_t o0 = (size_t)row * N + col;
                size_t o1 = (size_t)(row + 8) * N + col;
                float2 v0 = make_float2(acc[mt][nt][0], acc[mt][nt][1]);
                float2 v1 = make_float2(acc[mt][nt][2], acc[mt][nt][3]);
                if (atom) {
                    atomicAdd((float2*)(C + o0), v0);
                    atomicAdd((float2*)(C + o1), v1);
                } else {
                    if (R) {
                        float2 r0 = *(const float2*)(R + o0);
                        float2 r1 = *(const float2*)(R + o1);
                        v0.x += r0.x; v0.y += r0.y;
                        v1.x += r1.x; v1.y += r1.y;
                    }
                    *(float2*)(C + o0) = v0;
                    *(float2*)(C + o1) = v1;
                }
            }
        }
    }
}

// ================= host orchestration ======================================
extern "C" void kernel_launch(void* const* d_in, const int* in_sizes, int n_in,
                              void* d_out, int out_size) {
    (void)in_sizes; (void)n_in; (void)out_size;
    const int*   input_ids = (const int*)  d_in[0];
    const float* emb       = (const float*)d_in[1];
    const float* in_proj_w = (const float*)d_in[2];
    const float* conv_w    = (const float*)d_in[3];
    const float* conv_b    = (const float*)d_in[4];
    const float* x_proj_w  = (const float*)d_in[5];
    const float* dt_proj_w = (const float*)d_in[6];
    const float* dt_proj_b = (const float*)d_in[7];
    const float* A_log     = (const float*)d_in[8];
    const float* D_param   = (const float*)d_in[9];
    const float* out_proj_w= (const float*)d_in[10];
    const float* norm_w    = (const float*)d_in[11];
    const float* norm_f_w  = (const float*)d_in[12];
    float* logits = (float*)d_out;

    float *px, *pxz, *pxi, *pxdbl, *pdelta;
    __half *pemb16, *pinw16, *pxpw16, *poutw16, *pacth, *pactl;
    cudaGetSymbolAddress((void**)&px,      g_x);
    cudaGetSymbolAddress((void**)&pxz,     g_xz);
    cudaGetSymbolAddress((void**)&pxi,     g_xi);
    cudaGetSymbolAddress((void**)&pxdbl,   g_xdbl);
    cudaGetSymbolAddress((void**)&pdelta,  g_delta);
    cudaGetSymbolAddress((void**)&pemb16,  g_emb16);
    cudaGetSymbolAddress((void**)&pinw16,  g_inw16);
    cudaGetSymbolAddress((void**)&pxpw16,  g_xpw16);
    cudaGetSymbolAddress((void**)&poutw16, g_outw16);
    cudaGetSymbolAddress((void**)&pacth,   g_acth);
    cudaGetSymbolAddress((void**)&pactl,   g_actl);

    cudaFuncSetAttribute(mma_gemm, cudaFuncAttributeMaxDynamicSharedMemorySize, GSMEM);

    // weight fp16 rounding (once per launch)
    {
        int n4 = NVOCAB * DM / 4;
        round_kernel<<<(n4 + 255) / 256, 256>>>(emb, pemb16, n4);
        n4 = NLAYER * 2 * DI * DM / 4;
        round_kernel<<<(n4 + 255) / 256, 256>>>(in_proj_w, pinw16, n4);
        n4 = NLAYER * 80 * DI / 4;
        round_kernel<<<(n4 + 255) / 256, 256>>>(x_proj_w, pxpw16, n4);
        n4 = NLAYER * DM * DI / 4;
        round_kernel<<<(n4 + 255) / 256, 256>>>(out_proj_w, poutw16, n4);
    }

    embed_kernel<<<SEQ, 256>>>(input_ids, emb, px);

    for (int i = 0; i < NLAYER; i++) {
        rmsnorm_split_kernel<<<SEQ, 256>>>(px, norm_w + (size_t)i * DM, pacth, pactl);
        // in_proj (2-term): (2048,768) x (3072,768)^T
        mma_gemm<<<dim3(SEQ / 128, 2 * DI / 128), 256, GSMEM>>>(
            pacth, pactl, pinw16 + (size_t)i * 2 * DI * DM,
            pxz, nullptr, 2 * DI, DM);
        conv_silu_kernel<<<(SEQ * DI + 255) / 256, 256>>>(
            pxz, conv_w + (size_t)i * DI * 4, conv_b + (size_t)i * DI,
            pxi, pacth, pactl);
        // x_proj (2-term, split-K=16): (2048,1536) x (80,1536)^T
        zero_kernel<<<(SEQ * 80 + 255) / 256, 256>>>(pxdbl, SEQ * 80);
        mma_gemm<<<dim3(SEQ / 128, 1, 16), 256, GSMEM>>>(
            pacth, pactl, pxpw16 + (size_t)i * 80 * DI,
            pxdbl, nullptr, 80, DI);
        dtproj_kernel<<<dim3(DI / 128, SEQ / 16), 128>>>(
            pxdbl, dt_proj_w + (size_t)i * DI * DTR, dt_proj_b + (size_t)i * DI, pdelta);
        scan_kernel<<<DI / 8, 128>>>(
            pxdbl, pdelta, pxi, pxz,
            A_log + (size_t)i * DI * DS, D_param + (size_t)i * DI, pacth, pactl);
        // out_proj (1-term, split-K=4): accumulate into px (residual resident)
        mma_gemm<<<dim3(SEQ / 128, DM / 128, 4), 256, GSMEM>>>(
            pacth, nullptr, poutw16 + (size_t)i * DM * DI,
            px, nullptr, DM, DI);
    }

    rmsnorm_split_kernel<<<SEQ, 256>>>(px, norm_f_w, pacth, pactl);
    // logits (1-term): (2048,768) x (50264,768)^T
    mma_gemm<<<dim3(SEQ / 128, (NVOCAB + 127) / 128), 256, GSMEM>>>(
        pacth, nullptr, pemb16, logits, nullptr, NVOCAB, DM);
}